// round 1
// baseline (speedup 1.0000x reference)
#include <cuda_runtime.h>
#include <math.h>

#define Bm 4
#define Tt 2048
#define Cc 1024
#define Hh 16
#define Dd 64
#define Mrows (Bm*Tt)   // 8192

// Scratch: device globals (no runtime allocation allowed).
__device__ float g_Q[Bm*Hh*Tt*Dd];   // [B,H,T,D]
__device__ float g_K[Bm*Hh*Tt*Dd];
__device__ float g_V[Bm*Hh*Tt*Dd];
__device__ float g_Y[Mrows*Cc];      // [B,T,C]

// ---------------------------------------------------------------------------
// GEMM: out = x @ W^T + b.  64x64 tile, BK=16, 256 threads, 4x4 per thread.
// mode: writes into g_Q/g_K/g_V with head-split layout.
// ---------------------------------------------------------------------------
__global__ __launch_bounds__(256) void gemm_qkv(
    const float* __restrict__ x,
    const float* __restrict__ Wq, const float* __restrict__ bq,
    const float* __restrict__ Wk, const float* __restrict__ bk,
    const float* __restrict__ Wv, const float* __restrict__ bv)
{
    const int which = blockIdx.z;
    const float* __restrict__ W    = (which == 0) ? Wq : (which == 1) ? Wk : Wv;
    const float* __restrict__ bias = (which == 0) ? bq : (which == 1) ? bk : bv;
    float* __restrict__ out        = (which == 0) ? g_Q : (which == 1) ? g_K : g_V;

    __shared__ float As[16][68];
    __shared__ float Bs[16][68];

    const int tid = threadIdx.x;
    const int tx = tid & 15;
    const int ty = tid >> 4;
    const int rowBase = blockIdx.y * 64;
    const int colBase = blockIdx.x * 64;

    const int lr = tid >> 2;        // 0..63: row within tile
    const int lk = (tid & 3) * 4;   // k offset within BK

    float c[4][4] = {};

    for (int kt = 0; kt < Cc; kt += 16) {
        float4 a4 = *(const float4*)&x[(rowBase + lr) * Cc + kt + lk];
        float4 b4 = *(const float4*)&W[(colBase + lr) * Cc + kt + lk];
        As[lk + 0][lr] = a4.x; As[lk + 1][lr] = a4.y;
        As[lk + 2][lr] = a4.z; As[lk + 3][lr] = a4.w;
        Bs[lk + 0][lr] = b4.x; Bs[lk + 1][lr] = b4.y;
        Bs[lk + 2][lr] = b4.z; Bs[lk + 3][lr] = b4.w;
        __syncthreads();

        #pragma unroll
        for (int k = 0; k < 16; k++) {
            float4 av = *(const float4*)&As[k][ty * 4];
            float4 bv4 = *(const float4*)&Bs[k][tx * 4];
            float ar[4] = {av.x, av.y, av.z, av.w};
            float br[4] = {bv4.x, bv4.y, bv4.z, bv4.w};
            #pragma unroll
            for (int i = 0; i < 4; i++)
                #pragma unroll
                for (int j = 0; j < 4; j++)
                    c[i][j] = fmaf(ar[i], br[j], c[i][j]);
        }
        __syncthreads();
    }

    // epilogue: add bias, scatter to [B,H,T,D]
    #pragma unroll
    for (int i = 0; i < 4; i++) {
        int m = rowBase + ty * 4 + i;
        int b = m / Tt;
        int t = m % Tt;
        #pragma unroll
        for (int j = 0; j < 4; j++) {
            int n = colBase + tx * 4 + j;
            int h = n >> 6;           // n / D
            int d = n & 63;           // n % D
            float v = c[i][j] + bias[n];
            out[(((b * Hh) + h) * Tt + t) * Dd + d] = v;
        }
    }
}

// ---------------------------------------------------------------------------
// GEMM: d_out = g_Y @ Wp^T + bp (plain [M,C] output)
// ---------------------------------------------------------------------------
__global__ __launch_bounds__(256) void gemm_out(
    const float* __restrict__ W, const float* __restrict__ bias,
    float* __restrict__ out)
{
    __shared__ float As[16][68];
    __shared__ float Bs[16][68];

    const int tid = threadIdx.x;
    const int tx = tid & 15;
    const int ty = tid >> 4;
    const int rowBase = blockIdx.y * 64;
    const int colBase = blockIdx.x * 64;

    const int lr = tid >> 2;
    const int lk = (tid & 3) * 4;

    float c[4][4] = {};

    for (int kt = 0; kt < Cc; kt += 16) {
        float4 a4 = *(const float4*)&g_Y[(rowBase + lr) * Cc + kt + lk];
        float4 b4 = *(const float4*)&W[(colBase + lr) * Cc + kt + lk];
        As[lk + 0][lr] = a4.x; As[lk + 1][lr] = a4.y;
        As[lk + 2][lr] = a4.z; As[lk + 3][lr] = a4.w;
        Bs[lk + 0][lr] = b4.x; Bs[lk + 1][lr] = b4.y;
        Bs[lk + 2][lr] = b4.z; Bs[lk + 3][lr] = b4.w;
        __syncthreads();

        #pragma unroll
        for (int k = 0; k < 16; k++) {
            float4 av = *(const float4*)&As[k][ty * 4];
            float4 bv4 = *(const float4*)&Bs[k][tx * 4];
            float ar[4] = {av.x, av.y, av.z, av.w};
            float br[4] = {bv4.x, bv4.y, bv4.z, bv4.w};
            #pragma unroll
            for (int i = 0; i < 4; i++)
                #pragma unroll
                for (int j = 0; j < 4; j++)
                    c[i][j] = fmaf(ar[i], br[j], c[i][j]);
        }
        __syncthreads();
    }

    #pragma unroll
    for (int i = 0; i < 4; i++) {
        int m = rowBase + ty * 4 + i;
        #pragma unroll
        for (int j = 0; j < 4; j++) {
            int n = colBase + tx * 4 + j;
            out[m * Cc + n] = c[i][j] + bias[n];
        }
    }
}

// ---------------------------------------------------------------------------
// Flash attention, fp32, causal. Grid (T/128, B*H), 128 threads.
// One query row per thread; K/V tiles of 32 keys staged in smem.
// ---------------------------------------------------------------------------
__global__ __launch_bounds__(128) void attn_kernel()
{
    const int bh = blockIdx.y;          // 0..63
    const int qblk = blockIdx.x;        // 0..15
    const int b = bh >> 4;              // bh / H
    const int h = bh & 15;              // bh % H

    const float* __restrict__ Qg = g_Q + (size_t)bh * Tt * Dd;
    const float* __restrict__ Kg = g_K + (size_t)bh * Tt * Dd;
    const float* __restrict__ Vg = g_V + (size_t)bh * Tt * Dd;

    __shared__ float Ks[32 * 64];
    __shared__ float Vs[32 * 64];
    __shared__ float Ss[128][33];       // scores, conflict-free rows

    const int t = threadIdx.x;          // 0..127
    const int qg = qblk * 128 + t;      // global query row

    // q row in registers
    float q[64];
    #pragma unroll
    for (int i = 0; i < 16; i++) {
        float4 v4 = *(const float4*)&Qg[qg * Dd + i * 4];
        q[i * 4 + 0] = v4.x; q[i * 4 + 1] = v4.y;
        q[i * 4 + 2] = v4.z; q[i * 4 + 3] = v4.w;
    }

    float acc[64];
    #pragma unroll
    for (int i = 0; i < 64; i++) acc[i] = 0.0f;

    float mrun = -INFINITY;
    float lrun = 0.0f;
    const float scale = 0.125f;         // 1/sqrt(64)

    const int nk = qblk * 128 + 128;    // keys needed (exclusive)

    for (int kb = 0; kb < nk; kb += 32) {
        // cooperative load of 32x64 K and V tiles
        #pragma unroll
        for (int i = 0; i < 4; i++) {
            int o = (i * 128 + t) * 4;
            *(float4*)(Ks + o) = *(const float4*)(Kg + kb * Dd + o);
            *(float4*)(Vs + o) = *(const float4*)(Vg + kb * Dd + o);
        }
        __syncthreads();

        // phase 1: scores
        float tmax = -INFINITY;
        #pragma unroll 1
        for (int j = 0; j < 32; j++) {
            float s = -INFINITY;
            if (kb + j <= qg) {
                float s0 = 0.f, s1 = 0.f, s2 = 0.f, s3 = 0.f;
                #pragma unroll
                for (int dd = 0; dd < 16; dd++) {
                    float4 kv = *(const float4*)(Ks + j * 64 + dd * 4);
                    s0 = fmaf(q[dd * 4 + 0], kv.x, s0);
                    s1 = fmaf(q[dd * 4 + 1], kv.y, s1);
                    s2 = fmaf(q[dd * 4 + 2], kv.z, s2);
                    s3 = fmaf(q[dd * 4 + 3], kv.w, s3);
                }
                s = ((s0 + s1) + (s2 + s3)) * scale;
                tmax = fmaxf(tmax, s);
            }
            Ss[t][j] = s;
        }

        // phase 2: online softmax update + PV
        float newm = fmaxf(mrun, tmax);
        float corr = __expf(mrun - newm);   // exp(-inf - finite) = 0 on first tile
        lrun *= corr;
        #pragma unroll
        for (int d = 0; d < 64; d++) acc[d] *= corr;

        #pragma unroll 1
        for (int j = 0; j < 32; j++) {
            if (kb + j > qg) break;         // causal: rest of tile masked
            float p = __expf(Ss[t][j] - newm);
            lrun += p;
            #pragma unroll
            for (int dd = 0; dd < 16; dd++) {
                float4 vv = *(const float4*)(Vs + j * 64 + dd * 4);
                acc[dd * 4 + 0] = fmaf(p, vv.x, acc[dd * 4 + 0]);
                acc[dd * 4 + 1] = fmaf(p, vv.y, acc[dd * 4 + 1]);
                acc[dd * 4 + 2] = fmaf(p, vv.z, acc[dd * 4 + 2]);
                acc[dd * 4 + 3] = fmaf(p, vv.w, acc[dd * 4 + 3]);
            }
        }
        mrun = newm;
        __syncthreads();
    }

    // normalize and write y in [B,T,C] layout
    const float inv = 1.0f / lrun;
    float* __restrict__ yp = g_Y + ((size_t)(b * Tt + qg)) * Cc + h * Dd;
    #pragma unroll
    for (int dd = 0; dd < 16; dd++) {
        float4 o4;
        o4.x = acc[dd * 4 + 0] * inv;
        o4.y = acc[dd * 4 + 1] * inv;
        o4.z = acc[dd * 4 + 2] * inv;
        o4.w = acc[dd * 4 + 3] * inv;
        *(float4*)(yp + dd * 4) = o4;
    }
}

// ---------------------------------------------------------------------------
extern "C" void kernel_launch(void* const* d_in, const int* in_sizes, int n_in,
                              void* d_out, int out_size)
{
    const float* x  = (const float*)d_in[0];
    const float* Wq = (const float*)d_in[1];
    const float* bq = (const float*)d_in[2];
    const float* Wk = (const float*)d_in[3];
    const float* bk = (const float*)d_in[4];
    const float* Wv = (const float*)d_in[5];
    const float* bv = (const float*)d_in[6];
    const float* Wp = (const float*)d_in[7];
    const float* bp = (const float*)d_in[8];
    float* out = (float*)d_out;

    dim3 gQKV(Cc / 64, Mrows / 64, 3);    // 16 x 128 x 3
    gemm_qkv<<<gQKV, 256>>>(x, Wq, bq, Wk, bk, Wv, bv);

    dim3 gA(Tt / 128, Bm * Hh);           // 16 x 64
    attn_kernel<<<gA, 128>>>();

    dim3 gO(Cc / 64, Mrows / 64);         // 16 x 128
    gemm_out<<<gO, 256>>>(Wp, bp, out);
}

// round 4
// speedup vs baseline: 1.3301x; 1.3301x over previous
#include <cuda_runtime.h>
#include <cuda_bf16.h>
#include <math.h>
#include <stdint.h>

#define Bm 4
#define Tt 2048
#define Cc 1024
#define Hh 16
#define Dd 64
#define Mrows (Bm*Tt)   // 8192

// ------------------------- device-global scratch ---------------------------
__device__ float g_Q[Bm*Hh*Tt*Dd];   // [B,H,T,D] fp32
__device__ float g_K[Bm*Hh*Tt*Dd];
__device__ float g_V[Bm*Hh*Tt*Dd];
__device__ float g_Y[Mrows*Cc];      // [B,T,C] fp32 (attention output)

__device__ __nv_bfloat16 g_xh[Mrows*Cc];
__device__ __nv_bfloat16 g_xl[Mrows*Cc];
__device__ __nv_bfloat16 g_yh[Mrows*Cc];
__device__ __nv_bfloat16 g_yl[Mrows*Cc];
__device__ __nv_bfloat16 g_wh[4*Cc*Cc];   // Wq,Wk,Wv,Wp hi
__device__ __nv_bfloat16 g_wl[4*Cc*Cc];   // lo

// ---------------------------------------------------------------------------
// split fp32 -> bf16 hi + bf16 lo(residual). mode 0: x, 1..4: W(q,k,v,p), 5: Y
// ---------------------------------------------------------------------------
__global__ void split_kernel(const float* __restrict__ src, int n, int mode)
{
    int i = (blockIdx.x * blockDim.x + threadIdx.x) * 4;
    if (i >= n) return;

    const float* s;
    __nv_bfloat16 *hi, *lo;
    if (mode == 0)      { s = src;  hi = g_xh; lo = g_xl; }
    else if (mode <= 4) { s = src;  hi = g_wh + (mode-1)*Cc*Cc; lo = g_wl + (mode-1)*Cc*Cc; }
    else                { s = g_Y;  hi = g_yh; lo = g_yl; }

    float4 v = *(const float4*)(s + i);
    __nv_bfloat16 h0 = __float2bfloat16_rn(v.x);
    __nv_bfloat16 h1 = __float2bfloat16_rn(v.y);
    __nv_bfloat16 h2 = __float2bfloat16_rn(v.z);
    __nv_bfloat16 h3 = __float2bfloat16_rn(v.w);
    hi[i+0] = h0; hi[i+1] = h1; hi[i+2] = h2; hi[i+3] = h3;
    lo[i+0] = __float2bfloat16_rn(v.x - __bfloat162float(h0));
    lo[i+1] = __float2bfloat16_rn(v.y - __bfloat162float(h1));
    lo[i+2] = __float2bfloat16_rn(v.z - __bfloat162float(h2));
    lo[i+3] = __float2bfloat16_rn(v.w - __bfloat162float(h3));
}

// ---------------------------------------------------------------------------
// bf16 mma.sync m16n8k16, fp32 accum
// ---------------------------------------------------------------------------
__device__ __forceinline__ void mma16816(float* c, const uint32_t* a, const uint32_t* b)
{
    asm volatile(
        "mma.sync.aligned.m16n8k16.row.col.f32.bf16.bf16.f32 "
        "{%0,%1,%2,%3}, {%4,%5,%6,%7}, {%8,%9}, {%0,%1,%2,%3};\n"
        : "+f"(c[0]), "+f"(c[1]), "+f"(c[2]), "+f"(c[3])
        : "r"(a[0]), "r"(a[1]), "r"(a[2]), "r"(a[3]), "r"(b[0]), "r"(b[1]));
}

// ---------------------------------------------------------------------------
// Split-bf16 GEMM: C = A @ B^T + bias, with A = Ah+Al, B = Bh+Bl.
// A: [8192,1024], B(=W): [1024,1024] row-major (k contiguous -> mma col-major B).
// CTA tile 128(M) x 256(N), 8 warps as 2(M) x 4(N), warp tile 64x64.
// KC = 16 per chunk, single-buffered smem.
// mode 0/1/2: scatter into g_Q/g_K/g_V [B,H,T,D]; mode 3: linear into outp.
// ---------------------------------------------------------------------------
#define PITCH 24   // 16 + 8 pad (bf16 elements) -> conflict-free frag LDS

__global__ __launch_bounds__(256, 1) void gemm_mma(
    const __nv_bfloat16* __restrict__ Ah, const __nv_bfloat16* __restrict__ Al,
    const __nv_bfloat16* __restrict__ Bh, const __nv_bfloat16* __restrict__ Bl,
    const float* __restrict__ bias, float* __restrict__ outp, int mode)
{
    __shared__ __nv_bfloat16 sAh[128*PITCH];
    __shared__ __nv_bfloat16 sAl[128*PITCH];
    __shared__ __nv_bfloat16 sBh[256*PITCH];
    __shared__ __nv_bfloat16 sBl[256*PITCH];

    const int tid  = threadIdx.x;
    const int warp = tid >> 5;
    const int lane = tid & 31;
    const int warpM = warp & 1;       // 2 warps in M
    const int warpN = warp >> 1;      // 4 warps in N
    const int gid = lane >> 2;        // 0..7
    const int tig = lane & 3;         // 0..3

    const int rowBase = blockIdx.y * 128;
    const int colBase = blockIdx.x * 256;

    float acc[4][8][4];
    #pragma unroll
    for (int i = 0; i < 4; i++)
        #pragma unroll
        for (int j = 0; j < 8; j++)
            #pragma unroll
            for (int k = 0; k < 4; k++) acc[i][j][k] = 0.0f;

    for (int chunk = 0; chunk < Cc / 16; chunk++) {
        const int k0 = chunk * 16;

        // ---- load A tiles: 128 rows x 16 bf16 x 2 mats = 512 float4 ----
        #pragma unroll
        for (int it = 0; it < 2; it++) {
            int fa = tid + it * 256;              // 0..511
            int mat  = fa >> 8;                   // 0:h 1:l
            int r    = (fa & 255) >> 1;
            int part = fa & 1;
            const __nv_bfloat16* src = mat ? Al : Ah;
            __nv_bfloat16* dst = mat ? sAl : sAh;
            float4 v = *(const float4*)(src + (size_t)(rowBase + r) * Cc + k0 + part * 8);
            *(float4*)(dst + r * PITCH + part * 8) = v;
        }
        // ---- load B tiles: 256 rows x 16 bf16 x 2 mats = 1024 float4 ----
        #pragma unroll
        for (int it = 0; it < 4; it++) {
            int fb = tid + it * 256;              // 0..1023
            int mat  = fb >> 9;
            int r    = (fb & 511) >> 1;
            int part = fb & 1;
            const __nv_bfloat16* src = mat ? Bl : Bh;
            __nv_bfloat16* dst = mat ? sBl : sBh;
            float4 v = *(const float4*)(src + (size_t)(colBase + r) * Cc + k0 + part * 8);
            *(float4*)(dst + r * PITCH + part * 8) = v;
        }
        __syncthreads();

        // ---- B fragments for this warp (8 n-tiles x {h,l}) ----
        uint32_t bh[8][2], bl[8][2];
        #pragma unroll
        for (int ni = 0; ni < 8; ni++) {
            int n = warpN * 64 + ni * 8 + gid;
            bh[ni][0] = *(const uint32_t*)(sBh + n * PITCH + tig * 2);
            bh[ni][1] = *(const uint32_t*)(sBh + n * PITCH + tig * 2 + 8);
            bl[ni][0] = *(const uint32_t*)(sBl + n * PITCH + tig * 2);
            bl[ni][1] = *(const uint32_t*)(sBl + n * PITCH + tig * 2 + 8);
        }

        // ---- A fragments + MMAs ----
        #pragma unroll
        for (int mi = 0; mi < 4; mi++) {
            int r0 = warpM * 64 + mi * 16 + gid;
            uint32_t ah[4], al[4];
            ah[0] = *(const uint32_t*)(sAh + r0 * PITCH + tig * 2);
            ah[1] = *(const uint32_t*)(sAh + (r0 + 8) * PITCH + tig * 2);
            ah[2] = *(const uint32_t*)(sAh + r0 * PITCH + tig * 2 + 8);
            ah[3] = *(const uint32_t*)(sAh + (r0 + 8) * PITCH + tig * 2 + 8);
            al[0] = *(const uint32_t*)(sAl + r0 * PITCH + tig * 2);
            al[1] = *(const uint32_t*)(sAl + (r0 + 8) * PITCH + tig * 2);
            al[2] = *(const uint32_t*)(sAl + r0 * PITCH + tig * 2 + 8);
            al[3] = *(const uint32_t*)(sAl + (r0 + 8) * PITCH + tig * 2 + 8);

            #pragma unroll
            for (int ni = 0; ni < 8; ni++) {
                mma16816(acc[mi][ni], ah, bh[ni]);   // hi*hi
                mma16816(acc[mi][ni], ah, bl[ni]);   // hi*lo
                mma16816(acc[mi][ni], al, bh[ni]);   // lo*hi
            }
        }
        __syncthreads();
    }

    // ---- epilogue ----
    float* dst = (mode == 0) ? g_Q : (mode == 1) ? g_K : (mode == 2) ? g_V : outp;

    #pragma unroll
    for (int mi = 0; mi < 4; mi++) {
        #pragma unroll
        for (int ni = 0; ni < 8; ni++) {
            int m0 = rowBase + warpM * 64 + mi * 16 + gid;
            int n0 = colBase + warpN * 64 + ni * 8 + tig * 2;
            #pragma unroll
            for (int e = 0; e < 4; e++) {
                int m = m0 + ((e >> 1) ? 8 : 0);
                int n = n0 + (e & 1);
                float v = acc[mi][ni][e] + bias[n];
                if (mode < 3) {
                    int b = m >> 11;          // m / T
                    int t = m & 2047;         // m % T
                    int h = n >> 6;           // n / D
                    int d = n & 63;           // n % D
                    dst[(((size_t)(b * Hh + h)) * Tt + t) * Dd + d] = v;
                } else {
                    dst[(size_t)m * Cc + n] = v;
                }
            }
        }
    }
}

// ---------------------------------------------------------------------------
// Flash attention, fp32, causal (unchanged from R1).
// ---------------------------------------------------------------------------
__global__ __launch_bounds__(128) void attn_kernel()
{
    const int bh = blockIdx.y;
    const int qblk = blockIdx.x;
    const int b = bh >> 4;
    const int h = bh & 15;

    const float* __restrict__ Qg = g_Q + (size_t)bh * Tt * Dd;
    const float* __restrict__ Kg = g_K + (size_t)bh * Tt * Dd;
    const float* __restrict__ Vg = g_V + (size_t)bh * Tt * Dd;

    __shared__ float Ks[32 * 64];
    __shared__ float Vs[32 * 64];
    __shared__ float Ss[128][33];

    const int t = threadIdx.x;
    const int qg = qblk * 128 + t;

    float q[64];
    #pragma unroll
    for (int i = 0; i < 16; i++) {
        float4 v4 = *(const float4*)&Qg[qg * Dd + i * 4];
        q[i * 4 + 0] = v4.x; q[i * 4 + 1] = v4.y;
        q[i * 4 + 2] = v4.z; q[i * 4 + 3] = v4.w;
    }

    float acc[64];
    #pragma unroll
    for (int i = 0; i < 64; i++) acc[i] = 0.0f;

    float mrun = -INFINITY;
    float lrun = 0.0f;
    const float scale = 0.125f;

    const int nk = qblk * 128 + 128;

    for (int kb = 0; kb < nk; kb += 32) {
        #pragma unroll
        for (int i = 0; i < 4; i++) {
            int o = (i * 128 + t) * 4;
            *(float4*)(Ks + o) = *(const float4*)(Kg + kb * Dd + o);
            *(float4*)(Vs + o) = *(const float4*)(Vg + kb * Dd + o);
        }
        __syncthreads();

        float tmax = -INFINITY;
        #pragma unroll 1
        for (int j = 0; j < 32; j++) {
            float s = -INFINITY;
            if (kb + j <= qg) {
                float s0 = 0.f, s1 = 0.f, s2 = 0.f, s3 = 0.f;
                #pragma unroll
                for (int dd = 0; dd < 16; dd++) {
                    float4 kv = *(const float4*)(Ks + j * 64 + dd * 4);
                    s0 = fmaf(q[dd * 4 + 0], kv.x, s0);
                    s1 = fmaf(q[dd * 4 + 1], kv.y, s1);
                    s2 = fmaf(q[dd * 4 + 2], kv.z, s2);
                    s3 = fmaf(q[dd * 4 + 3], kv.w, s3);
                }
                s = ((s0 + s1) + (s2 + s3)) * scale;
                tmax = fmaxf(tmax, s);
            }
            Ss[t][j] = s;
        }

        float newm = fmaxf(mrun, tmax);
        float corr = __expf(mrun - newm);
        lrun *= corr;
        #pragma unroll
        for (int d = 0; d < 64; d++) acc[d] *= corr;

        #pragma unroll 1
        for (int j = 0; j < 32; j++) {
            if (kb + j > qg) break;
            float p = __expf(Ss[t][j] - newm);
            lrun += p;
            #pragma unroll
            for (int dd = 0; dd < 16; dd++) {
                float4 vv = *(const float4*)(Vs + j * 64 + dd * 4);
                acc[dd * 4 + 0] = fmaf(p, vv.x, acc[dd * 4 + 0]);
                acc[dd * 4 + 1] = fmaf(p, vv.y, acc[dd * 4 + 1]);
                acc[dd * 4 + 2] = fmaf(p, vv.z, acc[dd * 4 + 2]);
                acc[dd * 4 + 3] = fmaf(p, vv.w, acc[dd * 4 + 3]);
            }
        }
        mrun = newm;
        __syncthreads();
    }

    const float inv = 1.0f / lrun;
    float* __restrict__ yp = g_Y + ((size_t)(b * Tt + qg)) * Cc + h * Dd;
    #pragma unroll
    for (int dd = 0; dd < 16; dd++) {
        float4 o4;
        o4.x = acc[dd * 4 + 0] * inv;
        o4.y = acc[dd * 4 + 1] * inv;
        o4.z = acc[dd * 4 + 2] * inv;
        o4.w = acc[dd * 4 + 3] * inv;
        *(float4*)(yp + dd * 4) = o4;
    }
}

// ---------------------------------------------------------------------------
extern "C" void kernel_launch(void* const* d_in, const int* in_sizes, int n_in,
                              void* d_out, int out_size)
{
    const float* x  = (const float*)d_in[0];
    const float* Wq = (const float*)d_in[1];
    const float* bq = (const float*)d_in[2];
    const float* Wk = (const float*)d_in[3];
    const float* bk = (const float*)d_in[4];
    const float* Wv = (const float*)d_in[5];
    const float* bv = (const float*)d_in[6];
    const float* Wp = (const float*)d_in[7];
    const float* bp = (const float*)d_in[8];
    float* out = (float*)d_out;

    // resolve device-global symbol addresses (host API, no allocation)
    __nv_bfloat16 *xh, *xl, *yh, *yl, *wh, *wl;
    cudaGetSymbolAddress((void**)&xh, g_xh);
    cudaGetSymbolAddress((void**)&xl, g_xl);
    cudaGetSymbolAddress((void**)&yh, g_yh);
    cudaGetSymbolAddress((void**)&yl, g_yl);
    cudaGetSymbolAddress((void**)&wh, g_wh);
    cudaGetSymbolAddress((void**)&wl, g_wl);

    // 1. split inputs to bf16 hi/lo
    const int nx = Mrows * Cc;            // 8.4M
    const int nw = Cc * Cc;               // 1.05M
    split_kernel<<<nx / 4 / 256, 256>>>(x,  nx, 0);
    split_kernel<<<nw / 4 / 256, 256>>>(Wq, nw, 1);
    split_kernel<<<nw / 4 / 256, 256>>>(Wk, nw, 2);
    split_kernel<<<nw / 4 / 256, 256>>>(Wv, nw, 3);
    split_kernel<<<nw / 4 / 256, 256>>>(Wp, nw, 4);

    // 2. QKV projections on tensor cores
    dim3 gG(Cc / 256, Mrows / 128);       // 4 x 64
    gemm_mma<<<gG, 256>>>(xh, xl, wh + 0*nw, wl + 0*nw, bq, nullptr, 0);
    gemm_mma<<<gG, 256>>>(xh, xl, wh + 1*nw, wl + 1*nw, bk, nullptr, 1);
    gemm_mma<<<gG, 256>>>(xh, xl, wh + 2*nw, wl + 2*nw, bv, nullptr, 2);

    // 3. attention (fp32)
    dim3 gA(Tt / 128, Bm * Hh);
    attn_kernel<<<gA, 128>>>();

    // 4. split Y, out-projection
    split_kernel<<<nx / 4 / 256, 256>>>(nullptr, nx, 5);
    gemm_mma<<<gG, 256>>>(yh, yl, wh + 3*nw, wl + 3*nw, bp, out, 3);
}

// round 5
// speedup vs baseline: 2.3979x; 1.8027x over previous
#include <cuda_runtime.h>
#include <cuda_bf16.h>
#include <math.h>
#include <stdint.h>

#define Bm 4
#define Tt 2048
#define Cc 1024
#define Hh 16
#define Dd 64
#define Mrows (Bm*Tt)   // 8192

// ------------------------- device-global scratch ---------------------------
__device__ __nv_bfloat16 g_qh[Bm*Hh*Tt*Dd];  // [B,H,T,D] bf16 hi (pre-scaled 1/8)
__device__ __nv_bfloat16 g_ql[Bm*Hh*Tt*Dd];
__device__ __nv_bfloat16 g_kh[Bm*Hh*Tt*Dd];
__device__ __nv_bfloat16 g_kl[Bm*Hh*Tt*Dd];
__device__ __nv_bfloat16 g_vh[Bm*Hh*Tt*Dd];
__device__ __nv_bfloat16 g_vl[Bm*Hh*Tt*Dd];

__device__ __nv_bfloat16 g_xh[Mrows*Cc];
__device__ __nv_bfloat16 g_xl[Mrows*Cc];
__device__ __nv_bfloat16 g_yh[Mrows*Cc];
__device__ __nv_bfloat16 g_yl[Mrows*Cc];
__device__ __nv_bfloat16 g_wh[4*Cc*Cc];
__device__ __nv_bfloat16 g_wl[4*Cc*Cc];

// ---------------------------------------------------------------------------
// split fp32 -> bf16 hi + lo. mode 0: x, 1..4: W(q,k,v,p)
// ---------------------------------------------------------------------------
__global__ void split_kernel(const float* __restrict__ src, int n, int mode)
{
    int i = (blockIdx.x * blockDim.x + threadIdx.x) * 4;
    if (i >= n) return;

    __nv_bfloat16 *hi, *lo;
    if (mode == 0) { hi = g_xh; lo = g_xl; }
    else           { hi = g_wh + (mode-1)*Cc*Cc; lo = g_wl + (mode-1)*Cc*Cc; }

    float4 v = *(const float4*)(src + i);
    __nv_bfloat16 h0 = __float2bfloat16_rn(v.x);
    __nv_bfloat16 h1 = __float2bfloat16_rn(v.y);
    __nv_bfloat16 h2 = __float2bfloat16_rn(v.z);
    __nv_bfloat16 h3 = __float2bfloat16_rn(v.w);
    hi[i+0] = h0; hi[i+1] = h1; hi[i+2] = h2; hi[i+3] = h3;
    lo[i+0] = __float2bfloat16_rn(v.x - __bfloat162float(h0));
    lo[i+1] = __float2bfloat16_rn(v.y - __bfloat162float(h1));
    lo[i+2] = __float2bfloat16_rn(v.z - __bfloat162float(h2));
    lo[i+3] = __float2bfloat16_rn(v.w - __bfloat162float(h3));
}

// ---------------------------------------------------------------------------
// helpers
// ---------------------------------------------------------------------------
__device__ __forceinline__ void mma16816(float* c, const uint32_t* a, const uint32_t* b)
{
    asm volatile(
        "mma.sync.aligned.m16n8k16.row.col.f32.bf16.bf16.f32 "
        "{%0,%1,%2,%3}, {%4,%5,%6,%7}, {%8,%9}, {%0,%1,%2,%3};\n"
        : "+f"(c[0]), "+f"(c[1]), "+f"(c[2]), "+f"(c[3])
        : "r"(a[0]), "r"(a[1]), "r"(a[2]), "r"(a[3]), "r"(b[0]), "r"(b[1]));
}

__device__ __forceinline__ uint32_t sptr(const void* p)
{ return (uint32_t)__cvta_generic_to_shared(p); }

__device__ __forceinline__ void ldm4(uint32_t* r, uint32_t a)
{
    asm volatile("ldmatrix.sync.aligned.m8n8.x4.shared.b16 {%0,%1,%2,%3}, [%4];"
        : "=r"(r[0]), "=r"(r[1]), "=r"(r[2]), "=r"(r[3]) : "r"(a));
}
__device__ __forceinline__ void ldm4t(uint32_t* r, uint32_t a)
{
    asm volatile("ldmatrix.sync.aligned.m8n8.x4.trans.shared.b16 {%0,%1,%2,%3}, [%4];"
        : "=r"(r[0]), "=r"(r[1]), "=r"(r[2]), "=r"(r[3]) : "r"(a));
}

__device__ __forceinline__ uint32_t pk(float a, float b)
{
    __nv_bfloat162 t = __floats2bfloat162_rn(a, b);   // a -> low half
    return *(uint32_t*)&t;
}

// ---------------------------------------------------------------------------
// Split-bf16 GEMM. modes 0/1/2: epilogue splits to (g_qh,g_ql)/(g_kh,..)/(g_vh,..)
// in [B,H,T,D] layout (mode 0 pre-scaled by 0.125). mode 3: fp32 linear to outp.
// ---------------------------------------------------------------------------
#define PITCH 24

__global__ __launch_bounds__(256, 1) void gemm_mma(
    const __nv_bfloat16* __restrict__ Ah, const __nv_bfloat16* __restrict__ Al,
    const __nv_bfloat16* __restrict__ Bh, const __nv_bfloat16* __restrict__ Bl,
    const float* __restrict__ bias, float* __restrict__ outp, int mode)
{
    __shared__ __nv_bfloat16 sAh[128*PITCH];
    __shared__ __nv_bfloat16 sAl[128*PITCH];
    __shared__ __nv_bfloat16 sBh[256*PITCH];
    __shared__ __nv_bfloat16 sBl[256*PITCH];

    const int tid  = threadIdx.x;
    const int warp = tid >> 5;
    const int lane = tid & 31;
    const int warpM = warp & 1;
    const int warpN = warp >> 1;
    const int gid = lane >> 2;
    const int tig = lane & 3;

    const int rowBase = blockIdx.y * 128;
    const int colBase = blockIdx.x * 256;

    float acc[4][8][4];
    #pragma unroll
    for (int i = 0; i < 4; i++)
        #pragma unroll
        for (int j = 0; j < 8; j++)
            #pragma unroll
            for (int k = 0; k < 4; k++) acc[i][j][k] = 0.0f;

    for (int chunk = 0; chunk < Cc / 16; chunk++) {
        const int k0 = chunk * 16;

        #pragma unroll
        for (int it = 0; it < 2; it++) {
            int fa = tid + it * 256;
            int mat  = fa >> 8;
            int r    = (fa & 255) >> 1;
            int part = fa & 1;
            const __nv_bfloat16* src = mat ? Al : Ah;
            __nv_bfloat16* dst = mat ? sAl : sAh;
            float4 v = *(const float4*)(src + (size_t)(rowBase + r) * Cc + k0 + part * 8);
            *(float4*)(dst + r * PITCH + part * 8) = v;
        }
        #pragma unroll
        for (int it = 0; it < 4; it++) {
            int fb = tid + it * 256;
            int mat  = fb >> 9;
            int r    = (fb & 511) >> 1;
            int part = fb & 1;
            const __nv_bfloat16* src = mat ? Bl : Bh;
            __nv_bfloat16* dst = mat ? sBl : sBh;
            float4 v = *(const float4*)(src + (size_t)(colBase + r) * Cc + k0 + part * 8);
            *(float4*)(dst + r * PITCH + part * 8) = v;
        }
        __syncthreads();

        uint32_t bhf[8][2], blf[8][2];
        #pragma unroll
        for (int ni = 0; ni < 8; ni++) {
            int n = warpN * 64 + ni * 8 + gid;
            bhf[ni][0] = *(const uint32_t*)(sBh + n * PITCH + tig * 2);
            bhf[ni][1] = *(const uint32_t*)(sBh + n * PITCH + tig * 2 + 8);
            blf[ni][0] = *(const uint32_t*)(sBl + n * PITCH + tig * 2);
            blf[ni][1] = *(const uint32_t*)(sBl + n * PITCH + tig * 2 + 8);
        }

        #pragma unroll
        for (int mi = 0; mi < 4; mi++) {
            int r0 = warpM * 64 + mi * 16 + gid;
            uint32_t ah[4], al[4];
            ah[0] = *(const uint32_t*)(sAh + r0 * PITCH + tig * 2);
            ah[1] = *(const uint32_t*)(sAh + (r0 + 8) * PITCH + tig * 2);
            ah[2] = *(const uint32_t*)(sAh + r0 * PITCH + tig * 2 + 8);
            ah[3] = *(const uint32_t*)(sAh + (r0 + 8) * PITCH + tig * 2 + 8);
            al[0] = *(const uint32_t*)(sAl + r0 * PITCH + tig * 2);
            al[1] = *(const uint32_t*)(sAl + (r0 + 8) * PITCH + tig * 2);
            al[2] = *(const uint32_t*)(sAl + r0 * PITCH + tig * 2 + 8);
            al[3] = *(const uint32_t*)(sAl + (r0 + 8) * PITCH + tig * 2 + 8);

            #pragma unroll
            for (int ni = 0; ni < 8; ni++) {
                mma16816(acc[mi][ni], ah, bhf[ni]);
                mma16816(acc[mi][ni], ah, blf[ni]);
                mma16816(acc[mi][ni], al, bhf[ni]);
            }
        }
        __syncthreads();
    }

    // ---- epilogue ----
    if (mode == 3) {
        #pragma unroll
        for (int mi = 0; mi < 4; mi++) {
            #pragma unroll
            for (int ni = 0; ni < 8; ni++) {
                int m0 = rowBase + warpM * 64 + mi * 16 + gid;
                int n0 = colBase + warpN * 64 + ni * 8 + tig * 2;
                #pragma unroll
                for (int e = 0; e < 4; e++) {
                    int m = m0 + ((e >> 1) ? 8 : 0);
                    int n = n0 + (e & 1);
                    outp[(size_t)m * Cc + n] = acc[mi][ni][e] + bias[n];
                }
            }
        }
    } else {
        __nv_bfloat16* dh = (mode == 0) ? g_qh : (mode == 1) ? g_kh : g_vh;
        __nv_bfloat16* dl = (mode == 0) ? g_ql : (mode == 1) ? g_kl : g_vl;
        const float sc = (mode == 0) ? 0.125f : 1.0f;

        #pragma unroll
        for (int mi = 0; mi < 4; mi++) {
            #pragma unroll
            for (int ni = 0; ni < 8; ni++) {
                int m0 = rowBase + warpM * 64 + mi * 16 + gid;
                int n0 = colBase + warpN * 64 + ni * 8 + tig * 2;
                #pragma unroll
                for (int half = 0; half < 2; half++) {
                    int m = m0 + half * 8;
                    float v0 = (acc[mi][ni][half*2+0] + bias[n0])   * sc;
                    float v1 = (acc[mi][ni][half*2+1] + bias[n0+1]) * sc;
                    __nv_bfloat16 h0 = __float2bfloat16_rn(v0);
                    __nv_bfloat16 h1 = __float2bfloat16_rn(v1);
                    float l0 = v0 - __bfloat162float(h0);
                    float l1 = v1 - __bfloat162float(h1);
                    int b = m >> 11, t = m & 2047;
                    int h = n0 >> 6, d = n0 & 63;
                    size_t off = (((size_t)(b * Hh + h)) * Tt + t) * Dd + d;
                    __nv_bfloat162 hp; hp.x = h0; hp.y = h1;
                    *(uint32_t*)(dh + off) = *(uint32_t*)&hp;
                    *(uint32_t*)(dl + off) = pk(l0, l1);
                }
            }
        }
    }
}

// ---------------------------------------------------------------------------
// Flash attention on tensor cores, split-bf16, causal.
// Grid (16, 64), 256 threads (8 warps x 16 q-rows). K/V tiles of 64 keys.
// ---------------------------------------------------------------------------
__global__ __launch_bounds__(256, 1) void attn_mma()
{
    const int bh = blockIdx.y;
    const int qblk = (int)gridDim.x - 1 - (int)blockIdx.x;  // heavy blocks first
    const int tid = threadIdx.x;
    const int warp = tid >> 5;
    const int lane = tid & 31;
    const int g = lane >> 2;
    const int tig = lane & 3;

    const size_t base = (size_t)bh * Tt * Dd;

    __shared__ __align__(16) unsigned char sraw[36864];
    __nv_bfloat16* sQh = (__nv_bfloat16*)sraw;            // 128*72
    __nv_bfloat16* sQl = sQh + 128*72;
    __nv_bfloat16* sKh = (__nv_bfloat16*)sraw;            // 64*72 each
    __nv_bfloat16* sKl = sKh + 64*72;
    __nv_bfloat16* sVh = sKl + 64*72;
    __nv_bfloat16* sVl = sVh + 64*72;

    // ---- stage Q tile, build A-fragments ----
    #pragma unroll
    for (int it = 0; it < 4; it++) {
        int idx = tid + it * 256;             // 0..1023
        int r = idx >> 3, c8 = (idx & 7) * 8;
        size_t goff = base + (size_t)(qblk*128 + r) * Dd + c8;
        *(uint4*)(sQh + r*72 + c8) = *(const uint4*)(g_qh + goff);
        *(uint4*)(sQl + r*72 + c8) = *(const uint4*)(g_ql + goff);
    }
    __syncthreads();

    uint32_t qfh[4][4], qfl[4][4];
    {
        int row = warp*16 + (lane & 15);
        #pragma unroll
        for (int kt = 0; kt < 4; kt++) {
            int col = kt*16 + (lane >> 4) * 8;
            ldm4(qfh[kt], sptr(sQh + row*72 + col));
            ldm4(qfl[kt], sptr(sQl + row*72 + col));
        }
    }
    __syncthreads();

    float o[8][4];
    #pragma unroll
    for (int i = 0; i < 8; i++)
        #pragma unroll
        for (int j = 0; j < 4; j++) o[i][j] = 0.0f;

    float mA = -INFINITY, mB = -INFINITY, lA = 0.0f, lB = 0.0f;
    const int wr0 = qblk*128 + warp*16;
    const int nk = qblk*128 + 128;

    for (int kb = 0; kb < nk; kb += 64) {
        // ---- load K/V tiles (bf16 hi/lo) ----
        #pragma unroll
        for (int it = 0; it < 2; it++) {
            int idx = tid + it * 256;         // 0..511
            int r = idx >> 3, c8 = (idx & 7) * 8;
            size_t goff = base + (size_t)(kb + r) * Dd + c8;
            *(uint4*)(sKh + r*72 + c8) = *(const uint4*)(g_kh + goff);
            *(uint4*)(sKl + r*72 + c8) = *(const uint4*)(g_kl + goff);
            *(uint4*)(sVh + r*72 + c8) = *(const uint4*)(g_vh + goff);
            *(uint4*)(sVl + r*72 + c8) = *(const uint4*)(g_vl + goff);
        }
        __syncthreads();

        // ---- S = Q K^T (3-term split) ----
        float s[8][4];
        #pragma unroll
        for (int i = 0; i < 8; i++)
            #pragma unroll
            for (int j = 0; j < 4; j++) s[i][j] = 0.0f;

        #pragma unroll
        for (int kt = 0; kt < 4; kt++) {
            uint32_t kh4[4][4], kl4[4][4];
            #pragma unroll
            for (int i = 0; i < 4; i++) {
                int row = i*16 + (lane & 15);
                int col = kt*16 + (lane >> 4) * 8;
                ldm4(kh4[i], sptr(sKh + row*72 + col));
                ldm4(kl4[i], sptr(sKl + row*72 + col));
            }
            #pragma unroll
            for (int i = 0; i < 4; i++) {
                uint32_t b0h[2] = {kh4[i][0], kh4[i][2]};
                uint32_t b1h[2] = {kh4[i][1], kh4[i][3]};
                uint32_t b0l[2] = {kl4[i][0], kl4[i][2]};
                uint32_t b1l[2] = {kl4[i][1], kl4[i][3]};
                mma16816(s[2*i],   qfh[kt], b0h);
                mma16816(s[2*i],   qfh[kt], b0l);
                mma16816(s[2*i],   qfl[kt], b0h);
                mma16816(s[2*i+1], qfh[kt], b1h);
                mma16816(s[2*i+1], qfh[kt], b1l);
                mma16816(s[2*i+1], qfl[kt], b1h);
            }
        }

        // ---- causal mask (only near diagonal) ----
        if (kb + 64 > wr0) {
            int rA = wr0 + g, rB = rA + 8;
            #pragma unroll
            for (int nt = 0; nt < 8; nt++) {
                int c0 = kb + nt*8 + tig*2;
                if (c0     > rA) s[nt][0] = -INFINITY;
                if (c0 + 1 > rA) s[nt][1] = -INFINITY;
                if (c0     > rB) s[nt][2] = -INFINITY;
                if (c0 + 1 > rB) s[nt][3] = -INFINITY;
            }
        }

        // ---- online softmax ----
        float ma = -INFINITY, mb = -INFINITY;
        #pragma unroll
        for (int nt = 0; nt < 8; nt++) {
            ma = fmaxf(ma, fmaxf(s[nt][0], s[nt][1]));
            mb = fmaxf(mb, fmaxf(s[nt][2], s[nt][3]));
        }
        ma = fmaxf(ma, __shfl_xor_sync(0xffffffff, ma, 1));
        ma = fmaxf(ma, __shfl_xor_sync(0xffffffff, ma, 2));
        mb = fmaxf(mb, __shfl_xor_sync(0xffffffff, mb, 1));
        mb = fmaxf(mb, __shfl_xor_sync(0xffffffff, mb, 2));

        float nmA = fmaxf(mA, ma), nmB = fmaxf(mB, mb);
        float cA = __expf(mA - nmA), cB = __expf(mB - nmB);
        mA = nmA; mB = nmB;
        lA *= cA; lB *= cB;
        #pragma unroll
        for (int nt = 0; nt < 8; nt++) {
            o[nt][0] *= cA; o[nt][1] *= cA;
            o[nt][2] *= cB; o[nt][3] *= cB;
        }

        // ---- p = exp(s - m), split hi/lo, pack to A-frags ----
        uint32_t pah[4][4], pal[4][4];
        float suA = 0.0f, suB = 0.0f;
        #pragma unroll
        for (int nt = 0; nt < 8; nt++) {
            float p0 = __expf(s[nt][0] - nmA);
            float p1 = __expf(s[nt][1] - nmA);
            float p2 = __expf(s[nt][2] - nmB);
            float p3 = __expf(s[nt][3] - nmB);
            suA += p0 + p1; suB += p2 + p3;
            __nv_bfloat16 h0 = __float2bfloat16_rn(p0);
            __nv_bfloat16 h1 = __float2bfloat16_rn(p1);
            __nv_bfloat16 h2 = __float2bfloat16_rn(p2);
            __nv_bfloat16 h3 = __float2bfloat16_rn(p3);
            int kt = nt >> 1, hi2 = (nt & 1) * 2;
            __nv_bfloat162 t01; t01.x = h0; t01.y = h1;
            __nv_bfloat162 t23; t23.x = h2; t23.y = h3;
            pah[kt][hi2 + 0] = *(uint32_t*)&t01;
            pah[kt][hi2 + 1] = *(uint32_t*)&t23;
            pal[kt][hi2 + 0] = pk(p0 - __bfloat162float(h0), p1 - __bfloat162float(h1));
            pal[kt][hi2 + 1] = pk(p2 - __bfloat162float(h2), p3 - __bfloat162float(h3));
        }
        suA += __shfl_xor_sync(0xffffffff, suA, 1);
        suA += __shfl_xor_sync(0xffffffff, suA, 2);
        suB += __shfl_xor_sync(0xffffffff, suB, 1);
        suB += __shfl_xor_sync(0xffffffff, suB, 2);
        lA += suA; lB += suB;

        // ---- O += P V (3-term split) ----
        #pragma unroll
        for (int kt = 0; kt < 4; kt++) {
            uint32_t vh4[4][4], vl4[4][4];
            #pragma unroll
            for (int j = 0; j < 4; j++) {
                int row = kt*16 + (lane & 15);
                int col = j*16 + (lane >> 4) * 8;
                ldm4t(vh4[j], sptr(sVh + row*72 + col));
                ldm4t(vl4[j], sptr(sVl + row*72 + col));
            }
            #pragma unroll
            for (int j = 0; j < 4; j++) {
                uint32_t b0h[2] = {vh4[j][0], vh4[j][1]};
                uint32_t b1h[2] = {vh4[j][2], vh4[j][3]};
                uint32_t b0l[2] = {vl4[j][0], vl4[j][1]};
                uint32_t b1l[2] = {vl4[j][2], vl4[j][3]};
                mma16816(o[2*j],   pah[kt], b0h);
                mma16816(o[2*j],   pah[kt], b0l);
                mma16816(o[2*j],   pal[kt], b0h);
                mma16816(o[2*j+1], pah[kt], b1h);
                mma16816(o[2*j+1], pah[kt], b1l);
                mma16816(o[2*j+1], pal[kt], b1h);
            }
        }
        __syncthreads();
    }

    // ---- epilogue: normalize, split to bf16 hi/lo, write [B,T,C] ----
    const float iA = 1.0f / lA, iB = 1.0f / lB;
    const int b = bh >> 4, h = bh & 15;
    const int rA = qblk*128 + warp*16 + g;
    const size_t offA = ((size_t)(b * Tt + rA)) * Cc + h * 64;
    const size_t offB = offA + (size_t)8 * Cc;

    #pragma unroll
    for (int nt = 0; nt < 8; nt++) {
        int c = nt*8 + tig*2;
        float y0 = o[nt][0] * iA, y1 = o[nt][1] * iA;
        float y2 = o[nt][2] * iB, y3 = o[nt][3] * iB;
        __nv_bfloat16 h0 = __float2bfloat16_rn(y0);
        __nv_bfloat16 h1 = __float2bfloat16_rn(y1);
        __nv_bfloat16 h2 = __float2bfloat16_rn(y2);
        __nv_bfloat16 h3 = __float2bfloat16_rn(y3);
        __nv_bfloat162 tA; tA.x = h0; tA.y = h1;
        __nv_bfloat162 tB; tB.x = h2; tB.y = h3;
        *(uint32_t*)(g_yh + offA + c) = *(uint32_t*)&tA;
        *(uint32_t*)(g_yh + offB + c) = *(uint32_t*)&tB;
        *(uint32_t*)(g_yl + offA + c) = pk(y0 - __bfloat162float(h0), y1 - __bfloat162float(h1));
        *(uint32_t*)(g_yl + offB + c) = pk(y2 - __bfloat162float(h2), y3 - __bfloat162float(h3));
    }
}

// ---------------------------------------------------------------------------
extern "C" void kernel_launch(void* const* d_in, const int* in_sizes, int n_in,
                              void* d_out, int out_size)
{
    const float* x  = (const float*)d_in[0];
    const float* Wq = (const float*)d_in[1];
    const float* bq = (const float*)d_in[2];
    const float* Wk = (const float*)d_in[3];
    const float* bk = (const float*)d_in[4];
    const float* Wv = (const float*)d_in[5];
    const float* bv = (const float*)d_in[6];
    const float* Wp = (const float*)d_in[7];
    const float* bp = (const float*)d_in[8];
    float* out = (float*)d_out;

    __nv_bfloat16 *xh, *xl, *yh, *yl, *wh, *wl;
    cudaGetSymbolAddress((void**)&xh, g_xh);
    cudaGetSymbolAddress((void**)&xl, g_xl);
    cudaGetSymbolAddress((void**)&yh, g_yh);
    cudaGetSymbolAddress((void**)&yl, g_yl);
    cudaGetSymbolAddress((void**)&wh, g_wh);
    cudaGetSymbolAddress((void**)&wl, g_wl);

    const int nx = Mrows * Cc;
    const int nw = Cc * Cc;
    split_kernel<<<nx / 4 / 256, 256>>>(x,  nx, 0);
    split_kernel<<<nw / 4 / 256, 256>>>(Wq, nw, 1);
    split_kernel<<<nw / 4 / 256, 256>>>(Wk, nw, 2);
    split_kernel<<<nw / 4 / 256, 256>>>(Wv, nw, 3);
    split_kernel<<<nw / 4 / 256, 256>>>(Wp, nw, 4);

    dim3 gG(Cc / 256, Mrows / 128);
    gemm_mma<<<gG, 256>>>(xh, xl, wh + 0*nw, wl + 0*nw, bq, nullptr, 0);
    gemm_mma<<<gG, 256>>>(xh, xl, wh + 1*nw, wl + 1*nw, bk, nullptr, 1);
    gemm_mma<<<gG, 256>>>(xh, xl, wh + 2*nw, wl + 2*nw, bv, nullptr, 2);

    dim3 gA(Tt / 128, Bm * Hh);
    attn_mma<<<gA, 256>>>();

    gemm_mma<<<gG, 256>>>(yh, yl, wh + 3*nw, wl + 3*nw, bp, out, 3);
}

// round 7
// speedup vs baseline: 2.8157x; 1.1743x over previous
#include <cuda_runtime.h>
#include <cuda_bf16.h>
#include <math.h>
#include <stdint.h>

#define Bm 4
#define Tt 2048
#define Cc 1024
#define Hh 16
#define Dd 64
#define Mrows (Bm*Tt)   // 8192

// ------------------------- device-global scratch ---------------------------
__device__ __nv_bfloat16 g_qh[Bm*Hh*Tt*Dd];  // [B,H,T,D] bf16 hi (pre-scaled 1/8)
__device__ __nv_bfloat16 g_ql[Bm*Hh*Tt*Dd];
__device__ __nv_bfloat16 g_kh[Bm*Hh*Tt*Dd];
__device__ __nv_bfloat16 g_kl[Bm*Hh*Tt*Dd];
__device__ __nv_bfloat16 g_vh[Bm*Hh*Tt*Dd];
__device__ __nv_bfloat16 g_vl[Bm*Hh*Tt*Dd];

__device__ __nv_bfloat16 g_xh[Mrows*Cc];
__device__ __nv_bfloat16 g_xl[Mrows*Cc];
__device__ __nv_bfloat16 g_yh[Mrows*Cc];
__device__ __nv_bfloat16 g_yl[Mrows*Cc];
__device__ __nv_bfloat16 g_wh[4*Cc*Cc];
__device__ __nv_bfloat16 g_wl[4*Cc*Cc];

// ---------------------------------------------------------------------------
// split fp32 -> bf16 hi + lo. mode 0: x, 1..4: W(q,k,v,p)
// ---------------------------------------------------------------------------
__global__ void split_kernel(const float* __restrict__ src, int n, int mode)
{
    int i = (blockIdx.x * blockDim.x + threadIdx.x) * 4;
    if (i >= n) return;

    __nv_bfloat16 *hi, *lo;
    if (mode == 0) { hi = g_xh; lo = g_xl; }
    else           { hi = g_wh + (mode-1)*Cc*Cc; lo = g_wl + (mode-1)*Cc*Cc; }

    float4 v = *(const float4*)(src + i);
    __nv_bfloat16 h0 = __float2bfloat16_rn(v.x);
    __nv_bfloat16 h1 = __float2bfloat16_rn(v.y);
    __nv_bfloat16 h2 = __float2bfloat16_rn(v.z);
    __nv_bfloat16 h3 = __float2bfloat16_rn(v.w);
    hi[i+0] = h0; hi[i+1] = h1; hi[i+2] = h2; hi[i+3] = h3;
    lo[i+0] = __float2bfloat16_rn(v.x - __bfloat162float(h0));
    lo[i+1] = __float2bfloat16_rn(v.y - __bfloat162float(h1));
    lo[i+2] = __float2bfloat16_rn(v.z - __bfloat162float(h2));
    lo[i+3] = __float2bfloat16_rn(v.w - __bfloat162float(h3));
}

// ---------------------------------------------------------------------------
// helpers
// ---------------------------------------------------------------------------
__device__ __forceinline__ uint32_t sptr(const void* p)
{ uint32_t a; asm("{ .reg .u64 t; cvta.to.shared.u64 t, %1; cvt.u32.u64 %0, t; }" : "=r"(a) : "l"(p)); return a; }

__device__ __forceinline__ uint32_t pk(float a, float b)
{
    __nv_bfloat162 t = __floats2bfloat162_rn(a, b);
    return *(uint32_t*)&t;
}

__device__ __forceinline__ void mma16816(float* c, const uint32_t* a, const uint32_t* b)
{
    asm volatile(
        "mma.sync.aligned.m16n8k16.row.col.f32.bf16.bf16.f32 "
        "{%0,%1,%2,%3}, {%4,%5,%6,%7}, {%8,%9}, {%0,%1,%2,%3};\n"
        : "+f"(c[0]), "+f"(c[1]), "+f"(c[2]), "+f"(c[3])
        : "r"(a[0]), "r"(a[1]), "r"(a[2]), "r"(a[3]), "r"(b[0]), "r"(b[1]));
}
__device__ __forceinline__ void ldm4(uint32_t* r, uint32_t a)
{
    asm volatile("ldmatrix.sync.aligned.m8n8.x4.shared.b16 {%0,%1,%2,%3}, [%4];"
        : "=r"(r[0]), "=r"(r[1]), "=r"(r[2]), "=r"(r[3]) : "r"(a));
}
__device__ __forceinline__ void ldm4t(uint32_t* r, uint32_t a)
{
    asm volatile("ldmatrix.sync.aligned.m8n8.x4.trans.shared.b16 {%0,%1,%2,%3}, [%4];"
        : "=r"(r[0]), "=r"(r[1]), "=r"(r[2]), "=r"(r[3]) : "r"(a));
}

__device__ __forceinline__ void cpa16(uint32_t dst, const void* src)
{ asm volatile("cp.async.cg.shared.global [%0], [%1], 16;" :: "r"(dst), "l"(src)); }
#define CP_COMMIT() asm volatile("cp.async.commit_group;" ::: "memory")
#define CP_WAIT1()  asm volatile("cp.async.wait_group 1;" ::: "memory")
#define CP_WAIT0()  asm volatile("cp.async.wait_group 0;" ::: "memory")

// ---------------------------------------------------------------------------
// Split-bf16 GEMM, cp.async double-buffered. C = A @ W^T + bias.
// CTA tile 128(M) x 256(N), 8 warps (2M x 4N), warp tile 64x64, K-chunk 16.
// fused=1: blockIdx.z = which in {0,1,2} -> QKV split-epilogue.
// fused=0: mode 3 -> fp32 linear to outp.
// Dynamic smem: 2 buffers x (A 12288B + B 24576B) = 73728 B.
// ---------------------------------------------------------------------------
#define PITCH 24
#define BUFSZ 36864
#define GOFF_AH 0
#define GOFF_AL 6144
#define GOFF_BH 12288
#define GOFF_BL 24576

__global__ __launch_bounds__(256, 1) void gemm_db(
    const __nv_bfloat16* __restrict__ Ah, const __nv_bfloat16* __restrict__ Al,
    const __nv_bfloat16* __restrict__ Wh, const __nv_bfloat16* __restrict__ Wl,
    const float* __restrict__ b0, const float* __restrict__ b1,
    const float* __restrict__ b2,
    float* __restrict__ outp, int fused)
{
    extern __shared__ char smem[];
    const uint32_t sb = sptr(smem);

    const int which = blockIdx.z;
    const __nv_bfloat16* __restrict__ Bh = Wh + (size_t)which * Cc * Cc;
    const __nv_bfloat16* __restrict__ Bl = Wl + (size_t)which * Cc * Cc;
    const float* __restrict__ bias = (which == 0) ? b0 : (which == 1) ? b1 : b2;
    const int mode = fused ? which : 3;

    const int tid  = threadIdx.x;
    const int warp = tid >> 5;
    const int lane = tid & 31;
    const int warpM = warp & 1;
    const int warpN = warp >> 1;
    const int gid = lane >> 2;
    const int tig = lane & 3;

    const int rowBase = blockIdx.y * 128;
    const int colBase = blockIdx.x * 256;

    float acc[4][8][4];
    #pragma unroll
    for (int i = 0; i < 4; i++)
        #pragma unroll
        for (int j = 0; j < 8; j++)
            #pragma unroll
            for (int k = 0; k < 4; k++) acc[i][j][k] = 0.0f;

    // per-thread precomputed load indices
    const int a_r0 = (tid & 255) >> 1;        // used twice (hi/lo)
    const int a_part = tid & 1;

    // chunk loader: 1536 cp.async of 16B
    auto load_chunk = [&](int s, int buf) {
        const int k0 = s * 16;
        const uint32_t bb = sb + buf * BUFSZ;
        #pragma unroll
        for (int it = 0; it < 2; it++) {
            int fa = tid + it * 256;
            int mat  = fa >> 8;
            int r    = (fa & 255) >> 1;
            int part = fa & 1;
            const __nv_bfloat16* src = mat ? Al : Ah;
            uint32_t dst = bb + (mat ? GOFF_AL : GOFF_AH) + (r * PITCH + part * 8) * 2;
            cpa16(dst, src + (size_t)(rowBase + r) * Cc + k0 + part * 8);
        }
        #pragma unroll
        for (int it = 0; it < 4; it++) {
            int fb = tid + it * 256;
            int mat  = fb >> 9;
            int r    = (fb & 511) >> 1;
            int part = fb & 1;
            const __nv_bfloat16* src = mat ? Bl : Bh;
            uint32_t dst = bb + (mat ? GOFF_BL : GOFF_BH) + (r * PITCH + part * 8) * 2;
            cpa16(dst, src + (size_t)(colBase + r) * Cc + k0 + part * 8);
        }
    };

    load_chunk(0, 0);
    CP_COMMIT();

    for (int s = 0; s < Cc / 16; s++) {
        if (s + 1 < Cc / 16) {
            load_chunk(s + 1, (s + 1) & 1);
            CP_COMMIT();
            CP_WAIT1();
        } else {
            CP_WAIT0();
        }
        __syncthreads();

        const char* bb = smem + (s & 1) * BUFSZ;
        const __nv_bfloat16* sAh = (const __nv_bfloat16*)(bb + GOFF_AH);
        const __nv_bfloat16* sAl = (const __nv_bfloat16*)(bb + GOFF_AL);
        const __nv_bfloat16* sBh = (const __nv_bfloat16*)(bb + GOFF_BH);
        const __nv_bfloat16* sBl = (const __nv_bfloat16*)(bb + GOFF_BL);

        uint32_t bhf[8][2], blf[8][2];
        #pragma unroll
        for (int ni = 0; ni < 8; ni++) {
            int n = warpN * 64 + ni * 8 + gid;
            bhf[ni][0] = *(const uint32_t*)(sBh + n * PITCH + tig * 2);
            bhf[ni][1] = *(const uint32_t*)(sBh + n * PITCH + tig * 2 + 8);
            blf[ni][0] = *(const uint32_t*)(sBl + n * PITCH + tig * 2);
            blf[ni][1] = *(const uint32_t*)(sBl + n * PITCH + tig * 2 + 8);
        }

        #pragma unroll
        for (int mi = 0; mi < 4; mi++) {
            int r0 = warpM * 64 + mi * 16 + gid;
            uint32_t ah[4], al[4];
            ah[0] = *(const uint32_t*)(sAh + r0 * PITCH + tig * 2);
            ah[1] = *(const uint32_t*)(sAh + (r0 + 8) * PITCH + tig * 2);
            ah[2] = *(const uint32_t*)(sAh + r0 * PITCH + tig * 2 + 8);
            ah[3] = *(const uint32_t*)(sAh + (r0 + 8) * PITCH + tig * 2 + 8);
            al[0] = *(const uint32_t*)(sAl + r0 * PITCH + tig * 2);
            al[1] = *(const uint32_t*)(sAl + (r0 + 8) * PITCH + tig * 2);
            al[2] = *(const uint32_t*)(sAl + r0 * PITCH + tig * 2 + 8);
            al[3] = *(const uint32_t*)(sAl + (r0 + 8) * PITCH + tig * 2 + 8);

            #pragma unroll
            for (int ni = 0; ni < 8; ni++) {
                mma16816(acc[mi][ni], ah, bhf[ni]);
                mma16816(acc[mi][ni], ah, blf[ni]);
                mma16816(acc[mi][ni], al, bhf[ni]);
            }
        }
        __syncthreads();
    }

    // ---- epilogue ----
    if (mode == 3) {
        #pragma unroll
        for (int mi = 0; mi < 4; mi++) {
            #pragma unroll
            for (int ni = 0; ni < 8; ni++) {
                int m0 = rowBase + warpM * 64 + mi * 16 + gid;
                int n0 = colBase + warpN * 64 + ni * 8 + tig * 2;
                #pragma unroll
                for (int e = 0; e < 4; e++) {
                    int m = m0 + ((e >> 1) ? 8 : 0);
                    int n = n0 + (e & 1);
                    outp[(size_t)m * Cc + n] = acc[mi][ni][e] + bias[n];
                }
            }
        }
    } else {
        __nv_bfloat16* dh = (mode == 0) ? g_qh : (mode == 1) ? g_kh : g_vh;
        __nv_bfloat16* dl = (mode == 0) ? g_ql : (mode == 1) ? g_kl : g_vl;
        const float sc = (mode == 0) ? 0.125f : 1.0f;

        #pragma unroll
        for (int mi = 0; mi < 4; mi++) {
            #pragma unroll
            for (int ni = 0; ni < 8; ni++) {
                int m0 = rowBase + warpM * 64 + mi * 16 + gid;
                int n0 = colBase + warpN * 64 + ni * 8 + tig * 2;
                #pragma unroll
                for (int half = 0; half < 2; half++) {
                    int m = m0 + half * 8;
                    float v0 = (acc[mi][ni][half*2+0] + bias[n0])   * sc;
                    float v1 = (acc[mi][ni][half*2+1] + bias[n0+1]) * sc;
                    __nv_bfloat16 h0 = __float2bfloat16_rn(v0);
                    __nv_bfloat16 h1 = __float2bfloat16_rn(v1);
                    int b = m >> 11, t = m & 2047;
                    int h = n0 >> 6, d = n0 & 63;
                    size_t off = (((size_t)(b * Hh + h)) * Tt + t) * Dd + d;
                    __nv_bfloat162 hp; hp.x = h0; hp.y = h1;
                    *(uint32_t*)(dh + off) = *(uint32_t*)&hp;
                    *(uint32_t*)(dl + off) = pk(v0 - __bfloat162float(h0),
                                                v1 - __bfloat162float(h1));
                }
            }
        }
    }
}

// ---------------------------------------------------------------------------
// Flash attention on tensor cores, split-bf16, causal, cp.async double-buffered.
// Grid (16, 64), 256 threads (8 warps x 16 q-rows). K/V tiles of 64 keys.
// Dynamic smem: 2 x (Kh|Kl|Vh|Vl, 64x72 each) = 73728 B. Q staged in buf0.
// ---------------------------------------------------------------------------
#define ATT_ARR (64*72*2)     // 9216 B per array

__global__ __launch_bounds__(256, 1) void attn_mma()
{
    extern __shared__ char sm[];
    const uint32_t sbase = sptr(sm);

    const int bh = blockIdx.y;
    const int qblk = (int)gridDim.x - 1 - (int)blockIdx.x;
    const int tid = threadIdx.x;
    const int warp = tid >> 5;
    const int lane = tid & 31;
    const int g = lane >> 2;
    const int tig = lane & 3;

    const size_t base = (size_t)bh * Tt * Dd;

    // ---- stage Q tile into buf0, build A-fragments ----
    {
        __nv_bfloat16* sQh = (__nv_bfloat16*)sm;
        __nv_bfloat16* sQl = sQh + 128*72;
        #pragma unroll
        for (int it = 0; it < 4; it++) {
            int idx = tid + it * 256;
            int r = idx >> 3, c8 = (idx & 7) * 8;
            size_t goff = base + (size_t)(qblk*128 + r) * Dd + c8;
            *(uint4*)(sQh + r*72 + c8) = *(const uint4*)(g_qh + goff);
            *(uint4*)(sQl + r*72 + c8) = *(const uint4*)(g_ql + goff);
        }
    }
    __syncthreads();

    uint32_t qfh[4][4], qfl[4][4];
    {
        __nv_bfloat16* sQh = (__nv_bfloat16*)sm;
        __nv_bfloat16* sQl = sQh + 128*72;
        int row = warp*16 + (lane & 15);
        #pragma unroll
        for (int kt = 0; kt < 4; kt++) {
            int col = kt*16 + (lane >> 4) * 8;
            ldm4(qfh[kt], sptr(sQh + row*72 + col));
            ldm4(qfl[kt], sptr(sQl + row*72 + col));
        }
    }
    __syncthreads();

    float o[8][4];
    #pragma unroll
    for (int i = 0; i < 8; i++)
        #pragma unroll
        for (int j = 0; j < 4; j++) o[i][j] = 0.0f;

    float mA = -INFINITY, mB = -INFINITY, lA = 0.0f, lB = 0.0f;
    const int wr0 = qblk*128 + warp*16;
    const int ntiles = 2*qblk + 2;

    auto load_kv = [&](int kb, int buf) {
        const uint32_t bb = sbase + buf * BUFSZ;
        #pragma unroll
        for (int it = 0; it < 2; it++) {
            int idx = tid + it * 256;
            int r = idx >> 3, c8 = (idx & 7) * 8;
            size_t goff = base + (size_t)(kb + r) * Dd + c8;
            uint32_t so = (r*72 + c8) * 2;
            cpa16(bb + 0*ATT_ARR + so, g_kh + goff);
            cpa16(bb + 1*ATT_ARR + so, g_kl + goff);
            cpa16(bb + 2*ATT_ARR + so, g_vh + goff);
            cpa16(bb + 3*ATT_ARR + so, g_vl + goff);
        }
    };

    load_kv(0, 0);
    CP_COMMIT();

    for (int ti = 0; ti < ntiles; ti++) {
        const int kb = ti * 64;
        if (ti + 1 < ntiles) {
            load_kv(kb + 64, (ti + 1) & 1);
            CP_COMMIT();
            CP_WAIT1();
        } else {
            CP_WAIT0();
        }
        __syncthreads();

        const char* bb = sm + (ti & 1) * BUFSZ;
        const __nv_bfloat16* sKh = (const __nv_bfloat16*)(bb + 0*ATT_ARR);
        const __nv_bfloat16* sKl = (const __nv_bfloat16*)(bb + 1*ATT_ARR);
        const __nv_bfloat16* sVh = (const __nv_bfloat16*)(bb + 2*ATT_ARR);
        const __nv_bfloat16* sVl = (const __nv_bfloat16*)(bb + 3*ATT_ARR);

        // ---- S = Q K^T (3-term split) ----
        float s[8][4];
        #pragma unroll
        for (int i = 0; i < 8; i++)
            #pragma unroll
            for (int j = 0; j < 4; j++) s[i][j] = 0.0f;

        #pragma unroll
        for (int kt = 0; kt < 4; kt++) {
            uint32_t kh4[4][4], kl4[4][4];
            #pragma unroll
            for (int i = 0; i < 4; i++) {
                int row = i*16 + (lane & 15);
                int col = kt*16 + (lane >> 4) * 8;
                ldm4(kh4[i], sptr(sKh + row*72 + col));
                ldm4(kl4[i], sptr(sKl + row*72 + col));
            }
            #pragma unroll
            for (int i = 0; i < 4; i++) {
                uint32_t b0h[2] = {kh4[i][0], kh4[i][2]};
                uint32_t b1h[2] = {kh4[i][1], kh4[i][3]};
                uint32_t b0l[2] = {kl4[i][0], kl4[i][2]};
                uint32_t b1l[2] = {kl4[i][1], kl4[i][3]};
                mma16816(s[2*i],   qfh[kt], b0h);
                mma16816(s[2*i],   qfh[kt], b0l);
                mma16816(s[2*i],   qfl[kt], b0h);
                mma16816(s[2*i+1], qfh[kt], b1h);
                mma16816(s[2*i+1], qfh[kt], b1l);
                mma16816(s[2*i+1], qfl[kt], b1h);
            }
        }

        // ---- causal mask ----
        if (kb + 64 > wr0) {
            int rA = wr0 + g, rB = rA + 8;
            #pragma unroll
            for (int nt = 0; nt < 8; nt++) {
                int c0 = kb + nt*8 + tig*2;
                if (c0     > rA) s[nt][0] = -INFINITY;
                if (c0 + 1 > rA) s[nt][1] = -INFINITY;
                if (c0     > rB) s[nt][2] = -INFINITY;
                if (c0 + 1 > rB) s[nt][3] = -INFINITY;
            }
        }

        // ---- online softmax ----
        float ma = -INFINITY, mb = -INFINITY;
        #pragma unroll
        for (int nt = 0; nt < 8; nt++) {
            ma = fmaxf(ma, fmaxf(s[nt][0], s[nt][1]));
            mb = fmaxf(mb, fmaxf(s[nt][2], s[nt][3]));
        }
        ma = fmaxf(ma, __shfl_xor_sync(0xffffffff, ma, 1));
        ma = fmaxf(ma, __shfl_xor_sync(0xffffffff, ma, 2));
        mb = fmaxf(mb, __shfl_xor_sync(0xffffffff, mb, 1));
        mb = fmaxf(mb, __shfl_xor_sync(0xffffffff, mb, 2));

        float nmA = fmaxf(mA, ma), nmB = fmaxf(mB, mb);
        float cA = __expf(mA - nmA), cB = __expf(mB - nmB);
        mA = nmA; mB = nmB;
        lA *= cA; lB *= cB;
        #pragma unroll
        for (int nt = 0; nt < 8; nt++) {
            o[nt][0] *= cA; o[nt][1] *= cA;
            o[nt][2] *= cB; o[nt][3] *= cB;
        }

        uint32_t pah[4][4], pal[4][4];
        float suA = 0.0f, suB = 0.0f;
        #pragma unroll
        for (int nt = 0; nt < 8; nt++) {
            float p0 = __expf(s[nt][0] - nmA);
            float p1 = __expf(s[nt][1] - nmA);
            float p2 = __expf(s[nt][2] - nmB);
            float p3 = __expf(s[nt][3] - nmB);
            suA += p0 + p1; suB += p2 + p3;
            __nv_bfloat16 h0 = __float2bfloat16_rn(p0);
            __nv_bfloat16 h1 = __float2bfloat16_rn(p1);
            __nv_bfloat16 h2 = __float2bfloat16_rn(p2);
            __nv_bfloat16 h3 = __float2bfloat16_rn(p3);
            int kt = nt >> 1, hi2 = (nt & 1) * 2;
            __nv_bfloat162 t01; t01.x = h0; t01.y = h1;
            __nv_bfloat162 t23; t23.x = h2; t23.y = h3;
            pah[kt][hi2 + 0] = *(uint32_t*)&t01;
            pah[kt][hi2 + 1] = *(uint32_t*)&t23;
            pal[kt][hi2 + 0] = pk(p0 - __bfloat162float(h0), p1 - __bfloat162float(h1));
            pal[kt][hi2 + 1] = pk(p2 - __bfloat162float(h2), p3 - __bfloat162float(h3));
        }
        suA += __shfl_xor_sync(0xffffffff, suA, 1);
        suA += __shfl_xor_sync(0xffffffff, suA, 2);
        suB += __shfl_xor_sync(0xffffffff, suB, 1);
        suB += __shfl_xor_sync(0xffffffff, suB, 2);
        lA += suA; lB += suB;

        // ---- O += P V (3-term split) ----
        #pragma unroll
        for (int kt = 0; kt < 4; kt++) {
            uint32_t vh4[4][4], vl4[4][4];
            #pragma unroll
            for (int j = 0; j < 4; j++) {
                int row = kt*16 + (lane & 15);
                int col = j*16 + (lane >> 4) * 8;
                ldm4t(vh4[j], sptr(sVh + row*72 + col));
                ldm4t(vl4[j], sptr(sVl + row*72 + col));
            }
            #pragma unroll
            for (int j = 0; j < 4; j++) {
                uint32_t b0h[2] = {vh4[j][0], vh4[j][1]};
                uint32_t b1h[2] = {vh4[j][2], vh4[j][3]};
                uint32_t b0l[2] = {vl4[j][0], vl4[j][1]};
                uint32_t b1l[2] = {vl4[j][2], vl4[j][3]};
                mma16816(o[2*j],   pah[kt], b0h);
                mma16816(o[2*j],   pah[kt], b0l);
                mma16816(o[2*j],   pal[kt], b0h);
                mma16816(o[2*j+1], pah[kt], b1h);
                mma16816(o[2*j+1], pah[kt], b1l);
                mma16816(o[2*j+1], pal[kt], b1h);
            }
        }
        __syncthreads();
    }

    // ---- epilogue: normalize, split to bf16 hi/lo, write [B,T,C] ----
    const float iA = 1.0f / lA, iB = 1.0f / lB;
    const int b = bh >> 4, h = bh & 15;
    const int rA = qblk*128 + warp*16 + g;
    const size_t offA = ((size_t)(b * Tt + rA)) * Cc + h * 64;
    const size_t offB = offA + (size_t)8 * Cc;

    #pragma unroll
    for (int nt = 0; nt < 8; nt++) {
        int c = nt*8 + tig*2;
        float y0 = o[nt][0] * iA, y1 = o[nt][1] * iA;
        float y2 = o[nt][2] * iB, y3 = o[nt][3] * iB;
        __nv_bfloat16 h0 = __float2bfloat16_rn(y0);
        __nv_bfloat16 h1 = __float2bfloat16_rn(y1);
        __nv_bfloat16 h2 = __float2bfloat16_rn(y2);
        __nv_bfloat16 h3 = __float2bfloat16_rn(y3);
        __nv_bfloat162 tA; tA.x = h0; tA.y = h1;
        __nv_bfloat162 tB; tB.x = h2; tB.y = h3;
        *(uint32_t*)(g_yh + offA + c) = *(uint32_t*)&tA;
        *(uint32_t*)(g_yh + offB + c) = *(uint32_t*)&tB;
        *(uint32_t*)(g_yl + offA + c) = pk(y0 - __bfloat162float(h0), y1 - __bfloat162float(h1));
        *(uint32_t*)(g_yl + offB + c) = pk(y2 - __bfloat162float(h2), y3 - __bfloat162float(h3));
    }
}

// ---------------------------------------------------------------------------
extern "C" void kernel_launch(void* const* d_in, const int* in_sizes, int n_in,
                              void* d_out, int out_size)
{
    const float* x  = (const float*)d_in[0];
    const float* Wq = (const float*)d_in[1];
    const float* bq = (const float*)d_in[2];
    const float* Wk = (const float*)d_in[3];
    const float* bk = (const float*)d_in[4];
    const float* Wv = (const float*)d_in[5];
    const float* bv = (const float*)d_in[6];
    const float* Wp = (const float*)d_in[7];
    const float* bp = (const float*)d_in[8];
    float* out = (float*)d_out;

    __nv_bfloat16 *xh, *xl, *yh, *yl, *wh, *wl;
    cudaGetSymbolAddress((void**)&xh, g_xh);
    cudaGetSymbolAddress((void**)&xl, g_xl);
    cudaGetSymbolAddress((void**)&yh, g_yh);
    cudaGetSymbolAddress((void**)&yl, g_yl);
    cudaGetSymbolAddress((void**)&wh, g_wh);
    cudaGetSymbolAddress((void**)&wl, g_wl);

    cudaFuncSetAttribute(gemm_db, cudaFuncAttributeMaxDynamicSharedMemorySize, 2*BUFSZ);
    cudaFuncSetAttribute(attn_mma, cudaFuncAttributeMaxDynamicSharedMemorySize, 2*BUFSZ);

    const int nx = Mrows * Cc;
    const int nw = Cc * Cc;
    split_kernel<<<nx / 4 / 256, 256>>>(x,  nx, 0);
    split_kernel<<<nw / 4 / 256, 256>>>(Wq, nw, 1);
    split_kernel<<<nw / 4 / 256, 256>>>(Wk, nw, 2);
    split_kernel<<<nw / 4 / 256, 256>>>(Wv, nw, 3);
    split_kernel<<<nw / 4 / 256, 256>>>(Wp, nw, 4);

    // fused QKV: one launch, z = 3
    dim3 gQKV(Cc / 256, Mrows / 128, 3);
    gemm_db<<<gQKV, 256, 2*BUFSZ>>>(xh, xl, wh, wl, bq, bk, bv, nullptr, 1);

    dim3 gA(Tt / 128, Bm * Hh);
    attn_mma<<<gA, 256, 2*BUFSZ>>>();

    // out projection
    dim3 gO(Cc / 256, Mrows / 128, 1);
    gemm_db<<<gO, 256, 2*BUFSZ>>>(yh, yl, wh + 3*nw, wl + 3*nw, bp, bp, bp, out, 0);
}